// round 1
// baseline (speedup 1.0000x reference)
#include <cuda_runtime.h>

// Problem constants (fixed by setup_inputs)
#define BB   4
#define CC   128
#define HH   128
#define WW   128
#define WLOW 32
#define NLOW 1024   // 32*32
#define KTOP 2

// Scratch for top-2 results (no dynamic allocation allowed)
__device__ float g_w[BB * NLOW * 2];   // softmax weights already divided by 16
__device__ int   g_idx[BB * NLOW * 2]; // top-2 low-res block indices

// -------------------------------------------------------------------------
// Kernel 1: per-row top-2 over 1024 values + 2-way softmax (/16 folded in).
// One warp per row (B*NLOW = 4096 rows). Coalesced strided reads.
// -------------------------------------------------------------------------
__global__ void __launch_bounds__(256) topk_softmax_kernel(const float* __restrict__ attn)
{
    int warp = (blockIdx.x * blockDim.x + threadIdx.x) >> 5;
    int lane = threadIdx.x & 31;
    if (warp >= BB * NLOW) return;

    const float* row = attn + (size_t)warp * NLOW;

    float v0 = -1e30f, v1 = -1e30f;
    int   i0 = 0,      i1 = 0;

    #pragma unroll 8
    for (int j = lane; j < NLOW; j += 32) {
        float x = __ldg(row + j);
        if (x > v0)      { v1 = v0; i1 = i0; v0 = x; i0 = j; }
        else if (x > v1) { v1 = x;  i1 = j; }
    }

    // Butterfly merge of (top1, top2) pairs across the warp
    #pragma unroll
    for (int off = 16; off; off >>= 1) {
        float ov0 = __shfl_xor_sync(0xffffffffu, v0, off);
        int   oi0 = __shfl_xor_sync(0xffffffffu, i0, off);
        float ov1 = __shfl_xor_sync(0xffffffffu, v1, off);
        int   oi1 = __shfl_xor_sync(0xffffffffu, i1, off);
        if (ov0 > v0) {
            if (v0 > ov1) { v1 = v0;  i1 = i0;  }
            else          { v1 = ov1; i1 = oi1; }
            v0 = ov0; i0 = oi0;
        } else if (ov0 > v1) {
            v1 = ov0; i1 = oi0;
        }
    }

    if (lane == 0) {
        // softmax over {v0, v1}, then divide by r2=16
        float e   = __expf(v1 - v0);          // <= 1
        float inv = 1.0f / ((1.0f + e) * 16.0f);
        g_w[warp * 2 + 0]   = inv;            // w0/16
        g_w[warp * 2 + 1]   = e * inv;        // w1/16
        g_idx[warp * 2 + 0] = i0;
        g_idx[warp * 2 + 1] = i1;
    }
}

// -------------------------------------------------------------------------
// Kernel 2: one block per (b,c) plane.
//   Phase A: pool the 128x128 plane into 1024 smem block-sums (4x4 blocks).
//   Phase B: out_low[n] = w0*S[i0] + w1*S[i1]; broadcast to the 4x4 block.
// All global loads/stores are float4 and fully coalesced.
// -------------------------------------------------------------------------
__global__ void __launch_bounds__(256) resample_kernel(const float* __restrict__ v,
                                                       float* __restrict__ out)
{
    __shared__ float S[NLOW];

    const int plane = blockIdx.x;        // 0 .. B*C-1
    const int b     = plane >> 7;        // / CC
    const float* vp = v   + (size_t)plane * (HH * WW);
    float*       op = out + (size_t)plane * (HH * WW);
    const int t = threadIdx.x;           // 256 threads

    // Phase A: 4x4 block sums
    #pragma unroll
    for (int s = 0; s < NLOW / 256; s++) {
        int m  = t + s * 256;
        int br = m >> 5;                 // block row (0..31)
        int bc = m & 31;                 // block col (0..31)
        const float* p = vp + (br * 4) * WW + bc * 4;
        float4 r0 = *(const float4*)(p);
        float4 r1 = *(const float4*)(p + WW);
        float4 r2 = *(const float4*)(p + 2 * WW);
        float4 r3 = *(const float4*)(p + 3 * WW);
        S[m] = (r0.x + r0.y + r0.z + r0.w)
             + (r1.x + r1.y + r1.z + r1.w)
             + (r2.x + r2.y + r2.z + r2.w)
             + (r3.x + r3.y + r3.z + r3.w);
    }
    __syncthreads();

    // Phase B: weighted 2-point gather + 4x broadcast upsample write
    #pragma unroll
    for (int s = 0; s < NLOW / 256; s++) {
        int n  = t + s * 256;
        int gi = (b * NLOW + n) * 2;
        float w0 = g_w[gi];
        float w1 = g_w[gi + 1];
        int   i0 = g_idx[gi];
        int   i1 = g_idx[gi + 1];
        float val = fmaf(w0, S[i0], w1 * S[i1]);
        float4 vv = make_float4(val, val, val, val);
        int br = n >> 5;
        int bc = n & 31;
        float* q = op + (br * 4) * WW + bc * 4;
        *(float4*)(q)          = vv;
        *(float4*)(q + WW)     = vv;
        *(float4*)(q + 2 * WW) = vv;
        *(float4*)(q + 3 * WW) = vv;
    }
}

extern "C" void kernel_launch(void* const* d_in, const int* in_sizes, int n_in,
                              void* d_out, int out_size)
{
    const float* v_high = (const float*)d_in[0];   // (4,128,128,128)
    const float* attn   = (const float*)d_in[1];   // (4,1024,1024)
    float* out          = (float*)d_out;           // (4,128,128,128)

    // 4096 rows, one warp each -> 512 blocks x 256 threads
    topk_softmax_kernel<<<512, 256>>>(attn);
    // One block per (b,c) plane -> 512 blocks
    resample_kernel<<<BB * CC, 256>>>(v_high, out);
}

// round 2
// speedup vs baseline: 1.0230x; 1.0230x over previous
#include <cuda_runtime.h>

#define BB   4
#define CC   128
#define HH   128
#define WW   128
#define NLOW 1024          // 32*32 low-res positions
#define NPLANES (BB * CC)  // 512
#define NSUMS   (NPLANES * NLOW)  // 524288

// Scratch (no dynamic allocation allowed)
__device__ float  g_S[NSUMS];        // 4x4 block sums, 2 MB (L2-resident)
__device__ float4 g_wi[BB * NLOW];   // {w0/16, w1/16, bits(i0), bits(i1)}

// Grid split for the fused kernel
#define POOL_BLOCKS 2048   // 2048*256 threads = 524288 sums (1 thread/sum)
#define TOPK_BLOCKS 512    // 512*8 warps = 4096 rows (1 warp/row)

// -------------------------------------------------------------------------
// Kernel A: fused pooling + top-2/softmax (independent work, one launch)
// -------------------------------------------------------------------------
__global__ void __launch_bounds__(256) pool_topk_kernel(const float* __restrict__ v,
                                                        const float* __restrict__ attn)
{
    const int t = threadIdx.x;

    if (blockIdx.x < POOL_BLOCKS) {
        // ---- pooling: one thread per 4x4 block sum ----
        int m = blockIdx.x * 256 + t;          // 0 .. NSUMS-1
        int plane = m >> 10;                   // /NLOW
        int ml    = m & 1023;
        int br = ml >> 5;                      // 0..31
        int bc = ml & 31;                      // 0..31
        const float* p = v + (size_t)plane * (HH * WW) + (br * 4) * WW + bc * 4;
        float4 r0 = *(const float4*)(p);
        float4 r1 = *(const float4*)(p + WW);
        float4 r2 = *(const float4*)(p + 2 * WW);
        float4 r3 = *(const float4*)(p + 3 * WW);
        g_S[m] = (r0.x + r0.y + r0.z + r0.w)
               + (r1.x + r1.y + r1.z + r1.w)
               + (r2.x + r2.y + r2.z + r2.w)
               + (r3.x + r3.y + r3.z + r3.w);
        return;
    }

    // ---- top-2 + softmax: one warp per attn row ----
    int warp = (blockIdx.x - POOL_BLOCKS) * 8 + (t >> 5);  // 0..4095
    int lane = t & 31;

    const float4* row = (const float4*)(attn + (size_t)warp * NLOW);

    float v0 = -1e30f, v1 = -1e30f;
    int   i0 = 0,      i1 = 0;

    #pragma unroll
    for (int s = 0; s < 8; s++) {
        int j4 = lane + s * 32;               // float4 index
        float4 x = __ldg(row + j4);
        int base = j4 * 4;
        #pragma unroll
        for (int e = 0; e < 4; e++) {
            float xv = (e == 0) ? x.x : (e == 1) ? x.y : (e == 2) ? x.z : x.w;
            int   xi = base + e;
            if (xv > v0)      { v1 = v0; i1 = i0; v0 = xv; i0 = xi; }
            else if (xv > v1) { v1 = xv; i1 = xi; }
        }
    }

    #pragma unroll
    for (int off = 16; off; off >>= 1) {
        float ov0 = __shfl_xor_sync(0xffffffffu, v0, off);
        int   oi0 = __shfl_xor_sync(0xffffffffu, i0, off);
        float ov1 = __shfl_xor_sync(0xffffffffu, v1, off);
        int   oi1 = __shfl_xor_sync(0xffffffffu, i1, off);
        if (ov0 > v0) {
            if (v0 > ov1) { v1 = v0;  i1 = i0;  }
            else          { v1 = ov1; i1 = oi1; }
            v0 = ov0; i0 = oi0;
        } else if (ov0 > v1) {
            v1 = ov0; i1 = oi0;
        }
    }

    if (lane == 0) {
        float e   = __expf(v1 - v0);                 // <= 1
        float inv = 1.0f / ((1.0f + e) * 16.0f);     // /r2 folded in
        g_wi[warp] = make_float4(inv, e * inv,
                                 __int_as_float(i0), __int_as_float(i1));
    }
}

// -------------------------------------------------------------------------
// Kernel B: one thread per low-res output; gather 2 block-sums, broadcast
// the value to the 4x4 high-res block. Writes fully coalesced (float4).
// -------------------------------------------------------------------------
__global__ void __launch_bounds__(256) gather_kernel(float* __restrict__ out)
{
    int idx = blockIdx.x * 256 + threadIdx.x;   // 0 .. NSUMS-1
    int plane = idx >> 10;
    int n     = idx & 1023;
    int b     = plane >> 7;                     // /CC

    float4 wi = g_wi[b * NLOW + n];
    int i0 = __float_as_int(wi.z);
    int i1 = __float_as_int(wi.w);

    const float* Sp = g_S + (size_t)plane * NLOW;
    float val = fmaf(wi.x, __ldg(Sp + i0), wi.y * __ldg(Sp + i1));
    float4 vv = make_float4(val, val, val, val);

    int br = n >> 5;
    int bc = n & 31;
    float* q = out + (size_t)plane * (HH * WW) + (br * 4) * WW + bc * 4;
    *(float4*)(q)          = vv;
    *(float4*)(q + WW)     = vv;
    *(float4*)(q + 2 * WW) = vv;
    *(float4*)(q + 3 * WW) = vv;
}

extern "C" void kernel_launch(void* const* d_in, const int* in_sizes, int n_in,
                              void* d_out, int out_size)
{
    const float* v_high = (const float*)d_in[0];   // (4,128,128,128)
    const float* attn   = (const float*)d_in[1];   // (4,1024,1024)
    float* out          = (float*)d_out;           // (4,128,128,128)

    pool_topk_kernel<<<POOL_BLOCKS + TOPK_BLOCKS, 256>>>(v_high, attn);
    gather_kernel<<<NSUMS / 256, 256>>>(out);
}

// round 3
// speedup vs baseline: 1.0369x; 1.0136x over previous
#include <cuda_runtime.h>

#define BB   4
#define CC   128
#define HH   128
#define WW   128
#define NLOW 1024          // 32*32 low-res positions
#define NPLANES (BB * CC)  // 512
#define NSUMS   (NPLANES * NLOW)  // 524288

// Scratch (no dynamic allocation allowed)
__device__ float  g_S[NSUMS];        // 4x4 block sums, 2 MB (L2-resident)
__device__ float4 g_wi[BB * NLOW];   // {w0/16, w1/16, bits(i0), bits(i1)}

#define POOL_BLOCKS 2048   // 2048*256 threads = 524288 sums (1 thread/sum)
#define TOPK_BLOCKS 512    // 512*8 warps = 4096 rows (1 warp/row)

// -------------------------------------------------------------------------
// Kernel A: fused pooling + top-2/softmax (independent work, one launch)
// -------------------------------------------------------------------------
__global__ void __launch_bounds__(256) pool_topk_kernel(const float* __restrict__ v,
                                                        const float* __restrict__ attn)
{
    const int t = threadIdx.x;

    if (blockIdx.x < POOL_BLOCKS) {
        // ---- pooling: one thread per 4x4 block sum ----
        int m = blockIdx.x * 256 + t;          // 0 .. NSUMS-1
        int plane = m >> 10;                   // /NLOW
        int ml    = m & 1023;
        int br = ml >> 5;                      // 0..31
        int bc = ml & 31;                      // 0..31
        const float* p = v + (size_t)plane * (HH * WW) + (br * 4) * WW + bc * 4;
        float4 r0 = *(const float4*)(p);
        float4 r1 = *(const float4*)(p + WW);
        float4 r2 = *(const float4*)(p + 2 * WW);
        float4 r3 = *(const float4*)(p + 3 * WW);
        g_S[m] = (r0.x + r0.y + r0.z + r0.w)
               + (r1.x + r1.y + r1.z + r1.w)
               + (r2.x + r2.y + r2.z + r2.w)
               + (r3.x + r3.y + r3.z + r3.w);
        return;
    }

    // ---- top-2 + softmax: one warp per attn row ----
    int warp = (blockIdx.x - POOL_BLOCKS) * 8 + (t >> 5);  // 0..4095
    int lane = t & 31;

    const float4* row = (const float4*)(attn + (size_t)warp * NLOW);

    float v0 = -1e30f, v1 = -1e30f;
    int   i0 = 0,      i1 = 0;

    #pragma unroll
    for (int s = 0; s < 8; s++) {
        int j4 = lane + s * 32;               // float4 index
        float4 x = __ldg(row + j4);
        int base = j4 * 4;
        #pragma unroll
        for (int e = 0; e < 4; e++) {
            float xv = (e == 0) ? x.x : (e == 1) ? x.y : (e == 2) ? x.z : x.w;
            int   xi = base + e;
            if (xv > v0)      { v1 = v0; i1 = i0; v0 = xv; i0 = xi; }
            else if (xv > v1) { v1 = xv; i1 = xi; }
        }
    }

    #pragma unroll
    for (int off = 16; off; off >>= 1) {
        float ov0 = __shfl_xor_sync(0xffffffffu, v0, off);
        int   oi0 = __shfl_xor_sync(0xffffffffu, i0, off);
        float ov1 = __shfl_xor_sync(0xffffffffu, v1, off);
        int   oi1 = __shfl_xor_sync(0xffffffffu, i1, off);
        if (ov0 > v0) {
            if (v0 > ov1) { v1 = v0;  i1 = i0;  }
            else          { v1 = ov1; i1 = oi1; }
            v0 = ov0; i0 = oi0;
        } else if (ov0 > v1) {
            v1 = ov0; i1 = oi0;
        }
    }

    if (lane == 0) {
        float e   = __expf(v1 - v0);                 // <= 1
        float inv = 1.0f / ((1.0f + e) * 16.0f);     // /r2 folded in
        g_wi[warp] = make_float4(inv, e * inv,
                                 __int_as_float(i0), __int_as_float(i1));
    }
}

// -------------------------------------------------------------------------
// Kernel B: 4 blocks per plane. Stage the plane's 1024 block-sums in smem
// (coalesced float4), gather via LDS instead of scattered LDG, broadcast
// each value to its 4x4 high-res block with float4 stores.
// -------------------------------------------------------------------------
__global__ void __launch_bounds__(256) gather_kernel(float* __restrict__ out)
{
    __shared__ float S[NLOW];

    const int blk   = blockIdx.x;        // 0 .. 2047
    const int plane = blk >> 2;          // 4 blocks per plane
    const int q     = blk & 3;
    const int t     = threadIdx.x;
    const int b     = plane >> 7;        // /CC

    // Stage the 4 KB S plane: 256 threads x float4, fully coalesced (L2-hit)
    ((float4*)S)[t] = ((const float4*)(g_S + (size_t)plane * NLOW))[t];
    __syncthreads();

    const int n  = q * 256 + t;          // low-res position handled by this thread
    float4 wi = g_wi[b * NLOW + n];
    int i0 = __float_as_int(wi.z);
    int i1 = __float_as_int(wi.w);

    float val = fmaf(wi.x, S[i0], wi.y * S[i1]);
    float4 vv = make_float4(val, val, val, val);

    int br = n >> 5;
    int bc = n & 31;
    float* p = out + (size_t)plane * (HH * WW) + (br * 4) * WW + bc * 4;
    *(float4*)(p)          = vv;
    *(float4*)(p + WW)     = vv;
    *(float4*)(p + 2 * WW) = vv;
    *(float4*)(p + 3 * WW) = vv;
}

extern "C" void kernel_launch(void* const* d_in, const int* in_sizes, int n_in,
                              void* d_out, int out_size)
{
    const float* v_high = (const float*)d_in[0];   // (4,128,128,128)
    const float* attn   = (const float*)d_in[1];   // (4,1024,1024)
    float* out          = (float*)d_out;           // (4,128,128,128)

    pool_topk_kernel<<<POOL_BLOCKS + TOPK_BLOCKS, 256>>>(v_high, attn);
    gather_kernel<<<NPLANES * 4, 256>>>(out);
}

// round 4
// speedup vs baseline: 1.1533x; 1.1123x over previous
#include <cuda_runtime.h>

#define BB   4
#define CC   128
#define HH   128
#define WW   128
#define NLOW 1024          // 32*32 low-res positions
#define NPLANES (BB * CC)  // 512

// Scratch (no dynamic allocation allowed)
__device__ float4 g_wi[BB * NLOW];   // {w0/16, w1/16, bits(i0), bits(i1)}

// -------------------------------------------------------------------------
// Kernel 1: per-row top-2 over 1024 values + 2-way softmax (/16 folded in).
// One warp per row (B*NLOW = 4096 rows), float4 loads.
// -------------------------------------------------------------------------
__global__ void __launch_bounds__(256) topk_kernel(const float* __restrict__ attn)
{
    int warp = blockIdx.x * 8 + (threadIdx.x >> 5);   // 0..4095
    int lane = threadIdx.x & 31;

    const float4* row = (const float4*)(attn + (size_t)warp * NLOW);

    float v0 = -1e30f, v1 = -1e30f;
    int   i0 = 0,      i1 = 0;

    #pragma unroll
    for (int s = 0; s < 8; s++) {
        int j4 = lane + s * 32;
        float4 x = __ldg(row + j4);
        int base = j4 * 4;
        #pragma unroll
        for (int e = 0; e < 4; e++) {
            float xv = (e == 0) ? x.x : (e == 1) ? x.y : (e == 2) ? x.z : x.w;
            int   xi = base + e;
            if (xv > v0)      { v1 = v0; i1 = i0; v0 = xv; i0 = xi; }
            else if (xv > v1) { v1 = xv; i1 = xi; }
        }
    }

    #pragma unroll
    for (int off = 16; off; off >>= 1) {
        float ov0 = __shfl_xor_sync(0xffffffffu, v0, off);
        int   oi0 = __shfl_xor_sync(0xffffffffu, i0, off);
        float ov1 = __shfl_xor_sync(0xffffffffu, v1, off);
        int   oi1 = __shfl_xor_sync(0xffffffffu, i1, off);
        if (ov0 > v0) {
            if (v0 > ov1) { v1 = v0;  i1 = i0;  }
            else          { v1 = ov1; i1 = oi1; }
            v0 = ov0; i0 = oi0;
        } else if (ov0 > v1) {
            v1 = ov0; i1 = oi0;
        }
    }

    if (lane == 0) {
        float e   = __expf(v1 - v0);                 // <= 1
        float inv = 1.0f / ((1.0f + e) * 16.0f);     // /r2 folded in
        g_wi[warp] = make_float4(inv, e * inv,
                                 __int_as_float(i0), __int_as_float(i1));
    }
}

// -------------------------------------------------------------------------
// Kernel 2: one 1024-thread block per (b,c) plane.
//   Each thread pools one 4x4 block sum into smem (4 independent LDG.128),
//   prefetches its weight vector before the single barrier, then gathers
//   two sums and broadcast-writes its 4x4 output block (4x STG.128).
// -------------------------------------------------------------------------
__global__ void __launch_bounds__(1024, 2) resample_kernel(const float* __restrict__ v,
                                                           float* __restrict__ out)
{
    __shared__ float S[NLOW];

    const int plane = blockIdx.x;        // 0 .. 511
    const int b     = plane >> 7;        // / CC
    const int t     = threadIdx.x;       // 0 .. 1023  (= low-res position n)

    const int br = t >> 5;               // 0..31
    const int bc = t & 31;               // 0..31
    const size_t poff = (size_t)plane * (HH * WW) + (br * 4) * WW + bc * 4;

    // Prefetch the weight vector (independent of pooling) to overlap latency
    float4 wi = __ldg(&g_wi[b * NLOW + t]);

    // Pool one 4x4 block: 4 independent 16B loads, fully coalesced per warp
    const float* p = v + poff;
    float4 r0 = __ldg((const float4*)(p));
    float4 r1 = __ldg((const float4*)(p + WW));
    float4 r2 = __ldg((const float4*)(p + 2 * WW));
    float4 r3 = __ldg((const float4*)(p + 3 * WW));
    S[t] = (r0.x + r0.y + r0.z + r0.w)
         + (r1.x + r1.y + r1.z + r1.w)
         + (r2.x + r2.y + r2.z + r2.w)
         + (r3.x + r3.y + r3.z + r3.w);

    __syncthreads();

    // Gather two block sums, weighted combine, broadcast to 4x4 output block
    int i0 = __float_as_int(wi.z);
    int i1 = __float_as_int(wi.w);
    float val = fmaf(wi.x, S[i0], wi.y * S[i1]);
    float4 vv = make_float4(val, val, val, val);

    float* q = out + poff;
    *(float4*)(q)          = vv;
    *(float4*)(q + WW)     = vv;
    *(float4*)(q + 2 * WW) = vv;
    *(float4*)(q + 3 * WW) = vv;
}

extern "C" void kernel_launch(void* const* d_in, const int* in_sizes, int n_in,
                              void* d_out, int out_size)
{
    const float* v_high = (const float*)d_in[0];   // (4,128,128,128)
    const float* attn   = (const float*)d_in[1];   // (4,1024,1024)
    float* out          = (float*)d_out;           // (4,128,128,128)

    topk_kernel<<<512, 256>>>(attn);               // 4096 rows, 1 warp each
    resample_kernel<<<NPLANES, 1024>>>(v_high, out);
}